// round 2
// baseline (speedup 1.0000x reference)
#include <cuda_runtime.h>
#include <cuda_bf16.h>
#include <cstdint>

#define BB 2
#define EM 512
#define NH 8
#define DH 64
#define TT 2048
#define EPS 1e-5f

// ---------------- scratch (no allocation allowed) ----------------
__device__ float g_wn[4][EM * EM];            // standardized weights
__device__ float g_p[3][BB * EM * TT];        // projected q,k,v (LN in place)
__device__ float g_attn[BB * EM * TT];        // attention output

// ---------------- kernel 1: weight standardization ----------------
__global__ void std_weights(const float* __restrict__ W, float* __restrict__ Wn) {
    __shared__ float ssum[256], ssq[256];
    int row = blockIdx.x;
    const float* wr = W + row * EM;
    float s = 0.f, s2 = 0.f;
    for (int i = threadIdx.x; i < EM; i += 256) { float v = wr[i]; s += v; s2 += v * v; }
    ssum[threadIdx.x] = s; ssq[threadIdx.x] = s2;
    __syncthreads();
    for (int o = 128; o > 0; o >>= 1) {
        if (threadIdx.x < o) { ssum[threadIdx.x] += ssum[threadIdx.x + o]; ssq[threadIdx.x] += ssq[threadIdx.x + o]; }
        __syncthreads();
    }
    float mu  = ssum[0] * (1.f / EM);
    float var = ssq[0] * (1.f / EM) - mu * mu;
    float r   = rsqrtf(var + EPS);
    for (int i = threadIdx.x; i < EM; i += 256) Wn[row * EM + i] = (wr[i] - mu) * r;
}

// ---------------- kernel 2: projection SGEMM ----------------
// Y[b,o,t] = mask[b,t] * sum_i Wn[o,i] X[b,i,t] + bias[o]
// grid (T/64, EM/64, B), block 256, 4x4 micro-tiles
__global__ void __launch_bounds__(256) proj64(
    const float* __restrict__ Wn, const float* __restrict__ X,
    const float* __restrict__ bias, const int* __restrict__ mask,
    float* __restrict__ Y)
{
    __shared__ float As[16][68];   // As[k][m]
    __shared__ float Bs[16][64];   // Bs[k][t]
    int b  = blockIdx.z;
    int m0 = blockIdx.y * 64, t0 = blockIdx.x * 64;
    int tid = threadIdx.x;
    int tx = tid & 15, ty = tid >> 4;
    const float* Xb = X + (size_t)b * EM * TT;
    float acc[4][4] = {};

    for (int k0 = 0; k0 < EM; k0 += 16) {
        {   // A tile: W[m0+m][k0 .. k0+16)
            int m = tid >> 2, k4 = (tid & 3) * 4;
            float4 w = *(const float4*)(Wn + (size_t)(m0 + m) * EM + k0 + k4);
            As[k4 + 0][m] = w.x; As[k4 + 1][m] = w.y;
            As[k4 + 2][m] = w.z; As[k4 + 3][m] = w.w;
        }
        {   // B tile: X[k0+kk][t0 .. t0+64)
            int kk = tid >> 4, t4 = (tid & 15) * 4;
            *(float4*)&Bs[kk][t4] = *(const float4*)(Xb + (size_t)(k0 + kk) * TT + t0 + t4);
        }
        __syncthreads();
#pragma unroll
        for (int k = 0; k < 16; k++) {
            float4 a  = *(const float4*)&As[k][ty * 4];
            float4 bv = *(const float4*)&Bs[k][tx * 4];
            float av[4] = {a.x, a.y, a.z, a.w};
            float bw[4] = {bv.x, bv.y, bv.z, bv.w};
#pragma unroll
            for (int i = 0; i < 4; i++)
#pragma unroll
                for (int j = 0; j < 4; j++) acc[i][j] += av[i] * bw[j];
        }
        __syncthreads();
    }
#pragma unroll
    for (int i = 0; i < 4; i++) {
        int m = m0 + ty * 4 + i;
        float bi = bias[m];
#pragma unroll
        for (int j = 0; j < 4; j++) {
            int t = t0 + tx * 4 + j;
            float mk = (float)mask[b * TT + t];
            Y[(size_t)b * EM * TT + (size_t)m * TT + t] = acc[i][j] * mk + bi;
        }
    }
}

// ---------------- kernel 3: per-head LayerNorm over DH ----------------
// grid (T/256, NH, B), block 256; normalize x[b, h*64+d, t] over d
__global__ void ln_head_k(float* __restrict__ X,
                          const float* __restrict__ g, const float* __restrict__ be)
{
    int t = blockIdx.x * 256 + threadIdx.x;
    int h = blockIdx.y, b = blockIdx.z;
    float* base = X + (size_t)b * EM * TT + (size_t)h * DH * TT + t;
    float s = 0.f, s2 = 0.f;
    float v[DH];
#pragma unroll
    for (int d = 0; d < DH; d++) { v[d] = base[(size_t)d * TT]; s += v[d]; s2 += v[d] * v[d]; }
    float mu  = s * (1.f / DH);
    float var = s2 * (1.f / DH) - mu * mu;
    float r   = rsqrtf(var + EPS);
#pragma unroll
    for (int d = 0; d < DH; d++) base[(size_t)d * TT] = (v[d] - mu) * r * g[d] + be[d];
}

// ---------------- kernel 4: streaming attention ----------------
// grid (T/64, NH, B), block 256; 64q x 64k tiles, no-max softmax (|s|<1)
__global__ void __launch_bounds__(256) attn_kernel(
    const float* __restrict__ Q, const float* __restrict__ K, const float* __restrict__ V,
    const int* __restrict__ qmask, const int* __restrict__ kmask,
    float* __restrict__ Og)
{
    extern __shared__ float sm[];
    float* Qs  = sm;              // [64][68] as [d][q]
    float* KPs = sm + 64 * 68;    // K as [d][k], then P as [q][k]
    float* Vs  = sm + 2 * 64 * 68;// V transposed as [k][d]
    float* kms = sm + 3 * 64 * 68;// [64] key mask

    int b = blockIdx.z, h = blockIdx.y;
    int q0 = blockIdx.x * 64;
    int tid = threadIdx.x;
    int tx = tid & 15, ty = tid >> 4;
    const size_t headoff = (size_t)b * EM * TT + (size_t)h * DH * TT;

    {   // load Q tile -> Qs[d][q]
        int r = tid >> 4, c4 = (tid & 15) * 4;
#pragma unroll
        for (int rr = 0; rr < 64; rr += 16)
            *(float4*)&Qs[(r + rr) * 68 + c4] =
                *(const float4*)(Q + headoff + (size_t)(r + rr) * TT + q0 + c4);
    }

    float accO[4][4] = {};
    float lsum[4] = {};
    const float inv_scale = 1.0f / 181.0f;

    for (int k0 = 0; k0 < TT; k0 += 64) {
        __syncthreads();  // previous iter's reads of KPs/Vs done
        {   // load K -> KPs[d][k], V (transposed) -> Vs[k][d]
            int r = tid >> 4, c4 = (tid & 15) * 4;
#pragma unroll
            for (int rr = 0; rr < 64; rr += 16) {
                *(float4*)&KPs[(r + rr) * 68 + c4] =
                    *(const float4*)(K + headoff + (size_t)(r + rr) * TT + k0 + c4);
                float4 vv = *(const float4*)(V + headoff + (size_t)(r + rr) * TT + k0 + c4);
                Vs[(c4 + 0) * 68 + (r + rr)] = vv.x;
                Vs[(c4 + 1) * 68 + (r + rr)] = vv.y;
                Vs[(c4 + 2) * 68 + (r + rr)] = vv.z;
                Vs[(c4 + 3) * 68 + (r + rr)] = vv.w;
            }
            if (tid < 64) kms[tid] = (float)kmask[b * TT + k0 + tid];
        }
        __syncthreads();

        // S[q][k] = sum_d Qs[d][q] * KPs[d][k]
        float s[4][4] = {};
#pragma unroll
        for (int d = 0; d < 64; d++) {
            float4 a  = *(const float4*)&Qs[d * 68 + ty * 4];
            float4 bv = *(const float4*)&KPs[d * 68 + tx * 4];
            float av[4] = {a.x, a.y, a.z, a.w};
            float bw[4] = {bv.x, bv.y, bv.z, bv.w};
#pragma unroll
            for (int i = 0; i < 4; i++)
#pragma unroll
                for (int j = 0; j < 4; j++) s[i][j] += av[i] * bw[j];
        }

        // p = km ? exp(s/181) : 0  (|s| small -> no max subtraction needed)
        float km[4];
#pragma unroll
        for (int j = 0; j < 4; j++) km[j] = kms[tx * 4 + j];
#pragma unroll
        for (int i = 0; i < 4; i++)
#pragma unroll
            for (int j = 0; j < 4; j++) {
                float p = (km[j] > 0.f) ? __expf(s[i][j] * inv_scale) : 0.f;
                s[i][j] = p;
                lsum[i] += p;
            }

        __syncthreads();  // all S reads of KPs done -> safe to overwrite with P
#pragma unroll
        for (int i = 0; i < 4; i++) {
            float4 pv = make_float4(s[i][0], s[i][1], s[i][2], s[i][3]);
            *(float4*)&KPs[(ty * 4 + i) * 68 + tx * 4] = pv;
        }
        __syncthreads();

        // O[q][d] += sum_k P[q][k] * Vs[k][d]
#pragma unroll
        for (int k = 0; k < 64; k++) {
            float4 vv = *(const float4*)&Vs[k * 68 + tx * 4];
#pragma unroll
            for (int i = 0; i < 4; i++) {
                float p = KPs[(ty * 4 + i) * 68 + k];
                accO[i][0] += p * vv.x;
                accO[i][1] += p * vv.y;
                accO[i][2] += p * vv.z;
                accO[i][3] += p * vv.w;
            }
        }
    }

    // reduce row sums across the 16 tx lanes (within half-warp)
#pragma unroll
    for (int i = 0; i < 4; i++)
#pragma unroll
        for (int off = 8; off > 0; off >>= 1)
            lsum[i] += __shfl_xor_sync(0xffffffffu, lsum[i], off);

    __syncthreads();  // all P@V reads done -> reuse KPs for output staging
#pragma unroll
    for (int i = 0; i < 4; i++) {
        int q = q0 + ty * 4 + i;
        float sc = (qmask[b * TT + q] != 0) ? (1.f / lsum[i]) : 0.f;
#pragma unroll
        for (int j = 0; j < 4; j++)
            KPs[(tx * 4 + j) * 68 + (ty * 4 + i)] = accO[i][j] * sc;  // stage as [d][q]
    }
    __syncthreads();
    {   // coalesced store
        int r = tid >> 4, c4 = (tid & 15) * 4;
#pragma unroll
        for (int rr = 0; rr < 64; rr += 16)
            *(float4*)(Og + headoff + (size_t)(r + rr) * TT + q0 + c4) =
                *(const float4*)&KPs[(r + rr) * 68 + c4];
    }
}

// ---------------- launch ----------------
extern "C" void kernel_launch(void* const* d_in, const int* in_sizes, int n_in,
                              void* d_out, int out_size)
{
    const float* q  = (const float*)d_in[0];
    const float* k  = (const float*)d_in[1];
    const float* v  = (const float*)d_in[2];
    const int* qm   = (const int*)d_in[3];
    const int* km   = (const int*)d_in[4];
    const int* vm   = (const int*)d_in[5];
    const float* Wq = (const float*)d_in[6];
    const float* bq = (const float*)d_in[7];
    const float* Wk = (const float*)d_in[8];
    const float* bk = (const float*)d_in[9];
    const float* Wv = (const float*)d_in[10];
    const float* bv = (const float*)d_in[11];
    const float* Wo = (const float*)d_in[12];
    const float* bo = (const float*)d_in[13];
    const float* gq = (const float*)d_in[14];
    const float* eq = (const float*)d_in[15];
    const float* gk = (const float*)d_in[16];
    const float* ek = (const float*)d_in[17];
    const float* gv = (const float*)d_in[18];
    const float* ev = (const float*)d_in[19];
    float* out = (float*)d_out;

    void *pwn, *pp, *pa;
    cudaGetSymbolAddress(&pwn, g_wn);
    cudaGetSymbolAddress(&pp,  g_p);
    cudaGetSymbolAddress(&pa,  g_attn);
    float* wn0 = (float*)pwn;
    float* wn1 = wn0 + EM * EM;
    float* wn2 = wn1 + EM * EM;
    float* wn3 = wn2 + EM * EM;
    float* p0 = (float*)pp;
    float* p1 = p0 + BB * EM * TT;
    float* p2 = p1 + BB * EM * TT;
    float* ab = (float*)pa;

    // weight standardization
    std_weights<<<EM, 256>>>(Wq, wn0);
    std_weights<<<EM, 256>>>(Wk, wn1);
    std_weights<<<EM, 256>>>(Wv, wn2);
    std_weights<<<EM, 256>>>(Wo, wn3);

    dim3 gp(TT / 64, EM / 64, BB);
    proj64<<<gp, 256>>>(wn0, q, bq, qm, p0);
    proj64<<<gp, 256>>>(wn1, k, bk, km, p1);
    proj64<<<gp, 256>>>(wn2, v, bv, vm, p2);

    dim3 gl(TT / 256, NH, BB);
    ln_head_k<<<gl, 256>>>(p0, gq, eq);
    ln_head_k<<<gl, 256>>>(p1, gk, ek);
    ln_head_k<<<gl, 256>>>(p2, gv, ev);

    int smem = (3 * 64 * 68 + 64) * (int)sizeof(float);
    cudaFuncSetAttribute(attn_kernel, cudaFuncAttributeMaxDynamicSharedMemorySize, smem);
    dim3 ga(TT / 64, NH, BB);
    attn_kernel<<<ga, 256, smem>>>(p0, p1, p2, qm, km, ab);

    proj64<<<gp, 256>>>(wn3, ab, bo, qm, out);
}